// round 12
// baseline (speedup 1.0000x reference)
#include <cuda_runtime.h>
#include <cstddef>
#include <cstdint>

#define BB 2
#define TQ 2048
#define TK 2048
#define DIN 1024
#define DOUT 1024
#define NH 16
#define HD 64

// Scratch (no cudaMalloc allowed).
__device__ float g_q[(size_t)BB * TQ * DOUT];   // projected Q (fp32)
__device__ float g_k[(size_t)BB * TK * DOUT];   // projected K (fp32)
__device__ float g_v[(size_t)BB * TK * DOUT];   // projected V (fp32)
__device__ float g_x[(size_t)BB * TQ * DOUT];   // attn out (tf32-valued)
__device__ float g_cq[(size_t)BB * TQ * DIN];   // tf32-converted inputs
__device__ float g_ck[(size_t)BB * TK * DIN];
__device__ float g_cv[(size_t)BB * TK * DIN];
__device__ float g_cw[(size_t)4 * DOUT * DIN];  // tf32-converted Wq,Wk,Wv,Wo

// ---------------------------------------------------------------------------
// helpers
// ---------------------------------------------------------------------------
__device__ __forceinline__ unsigned f2tf(float f) {
    unsigned r;
    asm("cvt.rna.tf32.f32 %0, %1;" : "=r"(r) : "f"(f));
    return r;
}

__device__ __forceinline__ float ex2(float x) {
    float r;
    asm("ex2.approx.f32 %0, %1;" : "=f"(r) : "f"(x));
    return r;
}

__device__ __forceinline__ void mma_tf32(float c[4],
                                         unsigned a0, unsigned a1, unsigned a2, unsigned a3,
                                         unsigned b0, unsigned b1) {
    asm volatile(
        "mma.sync.aligned.m16n8k8.row.col.f32.tf32.tf32.f32 "
        "{%0,%1,%2,%3}, {%4,%5,%6,%7}, {%8,%9}, {%0,%1,%2,%3};"
        : "+f"(c[0]), "+f"(c[1]), "+f"(c[2]), "+f"(c[3])
        : "r"(a0), "r"(a1), "r"(a2), "r"(a3), "r"(b0), "r"(b1));
}

__device__ __forceinline__ void cp_async16(unsigned saddr, const void* g) {
    asm volatile("cp.async.ca.shared.global [%0], [%1], 16;" :: "r"(saddr), "l"(g));
}

__device__ __forceinline__ unsigned smem_u32(const void* p) {
    return (unsigned)__cvta_generic_to_shared(p);
}

__device__ __forceinline__ void ldsm_x4(unsigned& d0, unsigned& d1,
                                        unsigned& d2, unsigned& d3, unsigned addr) {
    asm volatile("ldmatrix.sync.aligned.m8n8.x4.shared.b16 {%0,%1,%2,%3}, [%4];"
                 : "=r"(d0), "=r"(d1), "=r"(d2), "=r"(d3) : "r"(addr));
}

// ---------------------------------------------------------------------------
// Elementwise tf32 pre-conversion (rna) — UNCHANGED from round 11.
// ---------------------------------------------------------------------------
struct CvtBatch {
    const float* src[4];
    float* dst[4];
};

__global__ __launch_bounds__(256) void cvt_tf32_kernel(CvtBatch p, int n4) {
    const float4* s = (const float4*)p.src[blockIdx.z];
    float4* d = (float4*)p.dst[blockIdx.z];
    for (int i = blockIdx.x * 256 + threadIdx.x; i < n4; i += gridDim.x * 256) {
        float4 v = s[i];
        uint4 o = {f2tf(v.x), f2tf(v.y), f2tf(v.z), f2tf(v.w)};
        *(uint4*)(d + i) = o;
    }
}

// ---------------------------------------------------------------------------
// Batched GEMM + bias — UNCHANGED from round 11 (cp.async + LDSM, passing).
// ---------------------------------------------------------------------------
#define GST 36
#define GEMM_BUF_WORDS (2 * 128 * GST)
#define GEMM_SMEM_BYTES (2 * GEMM_BUF_WORDS * 4)

struct GemmBatch {
    const float* x[3];
    const float* w[3];
    const float* b[3];
    float* y[3];
};

__global__ __launch_bounds__(256, 2) void gemm_tf32_kernel(
    GemmBatch p, int M, int N, int K) {
    extern __shared__ unsigned gsm[];
    const unsigned sb = smem_u32(gsm);

    const float* __restrict__ X = p.x[blockIdx.z];
    const float* __restrict__ W = p.w[blockIdx.z];
    const float* __restrict__ bias = p.b[blockIdx.z];
    float* __restrict__ Y = p.y[blockIdx.z];

    const int tid = threadIdx.x;
    const int lane = tid & 31;
    const int wid = tid >> 5;
    const int wm = wid >> 1;
    const int wn = wid & 1;
    const int g = lane >> 2;
    const int c = lane & 3;

    const int row0 = blockIdx.y * 128;
    const int col0 = blockIdx.x * 128;

    float acc[2][8][4];
#pragma unroll
    for (int mt = 0; mt < 2; mt++)
#pragma unroll
        for (int nt = 0; nt < 8; nt++)
#pragma unroll
            for (int j = 0; j < 4; j++) acc[mt][nt][j] = 0.0f;

    const int l7 = lane & 7;
    const int lb3 = (lane >> 3) & 1;
    const int lb4 = (lane >> 4) & 1;
    unsigned Aoff[2], Boff[4];
#pragma unroll
    for (int mt = 0; mt < 2; mt++) {
        int row = wm * 32 + mt * 16 + l7 + lb3 * 8;
        Aoff[mt] = (unsigned)((row * GST + lb4 * 4) * 4);
    }
#pragma unroll
    for (int pp = 0; pp < 4; pp++) {
        int row = wn * 64 + pp * 16 + l7 + lb4 * 8;
        Boff[pp] = (unsigned)((128 * GST + row * GST + lb3 * 4) * 4);
    }

    const int lrow = tid >> 3;
    const int lcol = (tid & 7) * 4;
    const int nslices = K >> 5;

    const float* xs = &X[(size_t)(row0 + lrow) * K + lcol];
    const float* ws = &W[(size_t)(col0 + lrow) * K + lcol];
    const unsigned aslot = (unsigned)((lrow * GST + lcol) * 4);
    const unsigned brow = (unsigned)(32 * GST * 4);
    const unsigned bofs = (unsigned)(128 * GST * 4);

#pragma unroll
    for (int i = 0; i < 4; i++) {
        cp_async16(sb + aslot + i * brow, xs + (size_t)i * 32 * K);
        cp_async16(sb + bofs + aslot + i * brow, ws + (size_t)i * 32 * K);
    }
    asm volatile("cp.async.commit_group;" ::: "memory");

    for (int t = 0; t < nslices; t++) {
        asm volatile("cp.async.wait_group 0;" ::: "memory");
        __syncthreads();

        if (t + 1 < nslices) {
            unsigned dst = sb + ((t + 1) & 1) * (unsigned)(GEMM_BUF_WORDS * 4);
            const float* xn = xs + (t + 1) * 32;
            const float* wn = ws + (t + 1) * 32;
#pragma unroll
            for (int i = 0; i < 4; i++) {
                cp_async16(dst + aslot + i * brow, xn + (size_t)i * 32 * K);
                cp_async16(dst + bofs + aslot + i * brow, wn + (size_t)i * 32 * K);
            }
            asm volatile("cp.async.commit_group;" ::: "memory");
        }

        const unsigned bufb = sb + (unsigned)((t & 1) * (GEMM_BUF_WORDS * 4));
#pragma unroll
        for (int ks = 0; ks < 4; ks++) {
            const unsigned kadd = (unsigned)(ks * 32);
            unsigned af0[4], af1[4], bf[8][2];
            ldsm_x4(af0[0], af0[1], af0[2], af0[3], bufb + Aoff[0] + kadd);
            ldsm_x4(af1[0], af1[1], af1[2], af1[3], bufb + Aoff[1] + kadd);
            ldsm_x4(bf[0][0], bf[0][1], bf[1][0], bf[1][1], bufb + Boff[0] + kadd);
            ldsm_x4(bf[2][0], bf[2][1], bf[3][0], bf[3][1], bufb + Boff[1] + kadd);
            ldsm_x4(bf[4][0], bf[4][1], bf[5][0], bf[5][1], bufb + Boff[2] + kadd);
            ldsm_x4(bf[6][0], bf[6][1], bf[7][0], bf[7][1], bufb + Boff[3] + kadd);
#pragma unroll
            for (int nt = 0; nt < 8; nt++) {
                mma_tf32(acc[0][nt], af0[0], af0[1], af0[2], af0[3], bf[nt][0], bf[nt][1]);
                mma_tf32(acc[1][nt], af1[0], af1[1], af1[2], af1[3], bf[nt][0], bf[nt][1]);
            }
        }
    }

#pragma unroll
    for (int mt = 0; mt < 2; mt++) {
        int r0 = row0 + wm * 32 + mt * 16 + g;
#pragma unroll
        for (int nt = 0; nt < 8; nt++) {
            int cc = col0 + wn * 64 + nt * 8 + c * 2;
            float b0 = bias[cc], b1 = bias[cc + 1];
            float2 lo = {acc[mt][nt][0] + b0, acc[mt][nt][1] + b1};
            float2 hi = {acc[mt][nt][2] + b0, acc[mt][nt][3] + b1};
            *(float2*)&Y[(size_t)r0 * N + cc] = lo;
            *(float2*)&Y[(size_t)(r0 + 8) * N + cc] = hi;
        }
    }
}

// ---------------------------------------------------------------------------
// Flash-attention, tf32 mma.sync, fixed-max softmax, FAT WARP TILES.
// CTA = 128 q rows, 4 warps (128 threads); each warp owns 32 q rows as TWO
// 16-row m-tiles, so K fragments (ldsm) and V fragments (scalar LDS) are
// reused across both -> smem traffic per HMMA drops ~44%.
//  - Q: linear rows (QST 68), rna-converted, scale folded; ldsm per (mt,ks).
//  - K: linear rows (KST 68), raw cp.async; 4 ldsm_x4 per ks (R10 mapping).
//  - V: permuted rows (VST 72), raw cp.async; s-registers are A-fragments.
// ---------------------------------------------------------------------------
#define QST 68
#define KST 68
#define VST 72
#define SMQ 0
#define SMK (128 * QST)
#define SMV (SMK + 2 * 64 * KST)
#define ATTN_WORDS (SMV + 2 * 64 * VST)
#define ATTN_BYTES (ATTN_WORDS * 4)
#define NKT (TK / 64)

__global__ __launch_bounds__(128, 2) void attn_tf32_kernel(
    const float* __restrict__ gq, const float* __restrict__ gk,
    const float* __restrict__ gv, float* __restrict__ gx) {
    extern __shared__ unsigned sm[];
    unsigned* Qs = sm + SMQ;
    const unsigned sb = smem_u32(sm);

    const int tid = threadIdx.x;
    const int lane = tid & 31;
    const int w = tid >> 5;        // 4 warps; warp owns q rows [w*32, w*32+32)
    const int g = lane >> 2;
    const int c = lane & 3;

    const int q0 = blockIdx.x * 128;
    const int h = blockIdx.y;
    const int b = blockIdx.z;

    const float SC = 0.125f * 1.44269504088896340736f;

    const float* Kg = gk + (size_t)b * TK * DOUT + h * HD;
    const float* Vg = gv + (size_t)b * TK * DOUT + h * HD;

    // loader indices: 2 threads per 64-word row (128 threads, 64 rows)
    const int key = tid >> 1;
    const int dcg = (tid & 1) * 32;   // word offset in row
    const int srow = (key & 56) | (((key & 7) >> 1) + ((key & 1) << 2));

    // ---- prologue: issue K0 + V0 via cp.async (8 x 16B each)
    {
        unsigned kdst = sb + (unsigned)((SMK + key * KST + dcg) * 4);
        unsigned vdst = sb + (unsigned)((SMV + srow * VST + dcg) * 4);
        const float* kp = &Kg[(size_t)key * DOUT + dcg];
        const float* vp = &Vg[(size_t)key * DOUT + dcg];
#pragma unroll
        for (int j = 0; j < 8; j++) {
            cp_async16(kdst + j * 16, kp + j * 4);
            cp_async16(vdst + j * 16, vp + j * 4);
        }
        asm volatile("cp.async.commit_group;" ::: "memory");
    }

    // ---- Q -> smem (linear, rna-converted, scaled); one full row per thread
    {
        const float* Qg = gq + ((size_t)b * TQ + q0 + tid) * DOUT + h * HD;
#pragma unroll
        for (int gi = 0; gi < 16; gi++) {
            float4 f = *(const float4*)&Qg[gi * 4];
            uint4 u = {f2tf(f.x * SC), f2tf(f.y * SC), f2tf(f.z * SC), f2tf(f.w * SC)};
            *(uint4*)&Qs[tid * QST + gi * 4] = u;
        }
    }

    // ldsm byte offsets (R10-verified mappings)
    const int l7 = lane & 7;
    const int lb3 = (lane >> 3) & 1;
    const int lb4 = (lane >> 4) & 1;
    unsigned Aoffq[2];
#pragma unroll
    for (int mt = 0; mt < 2; mt++)
        Aoffq[mt] = (unsigned)(((w * 32 + mt * 16 + l7 + lb3 * 8) * QST + lb4 * 4) * 4);
    unsigned Boffk[4];
#pragma unroll
    for (int pp = 0; pp < 4; pp++)
        Boffk[pp] = (unsigned)(((pp * 16 + l7 + lb4 * 8) * KST + lb3 * 4) * 4);

    float o[2][8][4];
#pragma unroll
    for (int mt = 0; mt < 2; mt++)
#pragma unroll
        for (int dt = 0; dt < 8; dt++)
#pragma unroll
            for (int j = 0; j < 4; j++) o[mt][dt][j] = 0.0f;
    float lrow[2][2] = {{0.0f, 0.0f}, {0.0f, 0.0f}};

    for (int t = 0; t < NKT; t++) {
        const int cb = t & 1;
        asm volatile("cp.async.wait_group 0;" ::: "memory");
        __syncthreads();

        // issue tile t+1 (overlaps compute of t)
        if (t + 1 < NKT) {
            const int nb = 1 - cb;
            unsigned kdst = sb + (unsigned)((SMK + nb * 64 * KST + key * KST + dcg) * 4);
            unsigned vdst = sb + (unsigned)((SMV + nb * 64 * VST + srow * VST + dcg) * 4);
            const float* kp = &Kg[(size_t)(t * 64 + 64 + key) * DOUT + dcg];
            const float* vp = &Vg[(size_t)(t * 64 + 64 + key) * DOUT + dcg];
#pragma unroll
            for (int j = 0; j < 8; j++) {
                cp_async16(kdst + j * 16, kp + j * 4);
                cp_async16(vdst + j * 16, vp + j * 4);
            }
            asm volatile("cp.async.commit_group;" ::: "memory");
        }

        const unsigned kbase = sb + (unsigned)((SMK + cb * 64 * KST) * 4);
        unsigned* Vb = sm + SMV + cb * (64 * VST);

        // ---- S = Q @ K^T, both m-tiles sharing K fragments
        float s[2][8][4];
#pragma unroll
        for (int mt = 0; mt < 2; mt++)
#pragma unroll
            for (int nt = 0; nt < 8; nt++)
#pragma unroll
                for (int j = 0; j < 4; j++) s[mt][nt][j] = 0.0f;
#pragma unroll
        for (int ks = 0; ks < 8; ks++) {
            const unsigned kadd = (unsigned)(ks * 32);
            unsigned qa0[4], qa1[4], kf[8][2];
            ldsm_x4(qa0[0], qa0[1], qa0[2], qa0[3], sb + (Aoffq[0] + kadd));
            ldsm_x4(qa1[0], qa1[1], qa1[2], qa1[3], sb + (Aoffq[1] + kadd));
            ldsm_x4(kf[0][0], kf[0][1], kf[1][0], kf[1][1], kbase + Boffk[0] + kadd);
            ldsm_x4(kf[2][0], kf[2][1], kf[3][0], kf[3][1], kbase + Boffk[1] + kadd);
            ldsm_x4(kf[4][0], kf[4][1], kf[5][0], kf[5][1], kbase + Boffk[2] + kadd);
            ldsm_x4(kf[6][0], kf[6][1], kf[7][0], kf[7][1], kbase + Boffk[3] + kadd);
#pragma unroll
            for (int nt = 0; nt < 8; nt++) {
                mma_tf32(s[0][nt], qa0[0], qa0[1], qa0[2], qa0[3], kf[nt][0], kf[nt][1]);
                mma_tf32(s[1][nt], qa1[0], qa1[1], qa1[2], qa1[3], kf[nt][0], kf[nt][1]);
            }
        }

        // ---- fixed-max softmax
#pragma unroll
        for (int mt = 0; mt < 2; mt++)
#pragma unroll
            for (int nt = 0; nt < 8; nt++) {
                s[mt][nt][0] = ex2(s[mt][nt][0]);
                s[mt][nt][1] = ex2(s[mt][nt][1]);
                s[mt][nt][2] = ex2(s[mt][nt][2]);
                s[mt][nt][3] = ex2(s[mt][nt][3]);
                lrow[mt][0] += s[mt][nt][0] + s[mt][nt][1];
                lrow[mt][1] += s[mt][nt][2] + s[mt][nt][3];
            }

        // ---- O += P @ V, both m-tiles sharing V fragments
#pragma unroll
        for (int ks = 0; ks < 8; ks++) {
#pragma unroll
            for (int dt = 0; dt < 8; dt++) {
                unsigned b0 = Vb[(ks * 8 + c) * VST + dt * 8 + g];
                unsigned b1 = Vb[(ks * 8 + c + 4) * VST + dt * 8 + g];
                mma_tf32(o[0][dt], __float_as_uint(s[0][ks][0]), __float_as_uint(s[0][ks][2]),
                         __float_as_uint(s[0][ks][1]), __float_as_uint(s[0][ks][3]), b0, b1);
                mma_tf32(o[1][dt], __float_as_uint(s[1][ks][0]), __float_as_uint(s[1][ks][2]),
                         __float_as_uint(s[1][ks][1]), __float_as_uint(s[1][ks][3]), b0, b1);
            }
        }
    }

    // ---- final l reduction + write (epilogue emits tf32 values for oproj)
#pragma unroll
    for (int mt = 0; mt < 2; mt++) {
        float l0 = lrow[mt][0], l1 = lrow[mt][1];
        l0 += __shfl_xor_sync(0xffffffffu, l0, 1);
        l0 += __shfl_xor_sync(0xffffffffu, l0, 2);
        l1 += __shfl_xor_sync(0xffffffffu, l1, 1);
        l1 += __shfl_xor_sync(0xffffffffu, l1, 2);
        float inv0 = 1.0f / l0, inv1 = 1.0f / l1;
        size_t r0 = (size_t)b * TQ + q0 + w * 32 + mt * 16 + g;
#pragma unroll
        for (int dt = 0; dt < 8; dt++) {
            int cc = h * HD + dt * 8 + c * 2;
            uint2 lo = {f2tf(o[mt][dt][0] * inv0), f2tf(o[mt][dt][1] * inv0)};
            uint2 hi = {f2tf(o[mt][dt][2] * inv1), f2tf(o[mt][dt][3] * inv1)};
            *(uint2*)&gx[r0 * DOUT + cc] = lo;
            *(uint2*)&gx[(r0 + 8) * DOUT + cc] = hi;
        }
    }
}

// ---------------------------------------------------------------------------
// Launch
// ---------------------------------------------------------------------------
extern "C" void kernel_launch(void* const* d_in, const int* in_sizes, int n_in,
                              void* d_out, int out_size) {
    const float* q  = (const float*)d_in[0];
    const float* k  = (const float*)d_in[1];
    const float* v  = (const float*)d_in[2];
    const float* Wq = (const float*)d_in[3];
    const float* bq = (const float*)d_in[4];
    const float* Wk = (const float*)d_in[5];
    const float* bk = (const float*)d_in[6];
    const float* Wv = (const float*)d_in[7];
    const float* bv = (const float*)d_in[8];
    const float* Wo = (const float*)d_in[9];
    const float* bo = (const float*)d_in[10];
    float* out = (float*)d_out;

    float *pq, *pk, *pv, *px, *cq, *ck, *cv, *cw;
    cudaGetSymbolAddress((void**)&pq, g_q);
    cudaGetSymbolAddress((void**)&pk, g_k);
    cudaGetSymbolAddress((void**)&pv, g_v);
    cudaGetSymbolAddress((void**)&px, g_x);
    cudaGetSymbolAddress((void**)&cq, g_cq);
    cudaGetSymbolAddress((void**)&ck, g_ck);
    cudaGetSymbolAddress((void**)&cv, g_cv);
    cudaGetSymbolAddress((void**)&cw, g_cw);

    cudaFuncSetAttribute(gemm_tf32_kernel,
                         cudaFuncAttributeMaxDynamicSharedMemorySize,
                         GEMM_SMEM_BYTES);
    cudaFuncSetAttribute(attn_tf32_kernel,
                         cudaFuncAttributeMaxDynamicSharedMemorySize,
                         ATTN_BYTES);

    const size_t WSZ = (size_t)DOUT * DIN;

    CvtBatch ci;
    ci.src[0] = q;  ci.dst[0] = cq;
    ci.src[1] = k;  ci.dst[1] = ck;
    ci.src[2] = v;  ci.dst[2] = cv;
    ci.src[3] = q;  ci.dst[3] = cq;  // unused lane
    cvt_tf32_kernel<<<dim3(512, 1, 3), 256>>>(ci, (int)((size_t)BB * TQ * DIN / 4));

    CvtBatch cwb;
    cwb.src[0] = Wq; cwb.dst[0] = cw + 0 * WSZ;
    cwb.src[1] = Wk; cwb.dst[1] = cw + 1 * WSZ;
    cwb.src[2] = Wv; cwb.dst[2] = cw + 2 * WSZ;
    cwb.src[3] = Wo; cwb.dst[3] = cw + 3 * WSZ;
    cvt_tf32_kernel<<<dim3(256, 1, 4), 256>>>(cwb, (int)(WSZ / 4));

    GemmBatch proj;
    proj.x[0] = cq; proj.w[0] = cw + 0 * WSZ; proj.b[0] = bq; proj.y[0] = pq;
    proj.x[1] = ck; proj.w[1] = cw + 1 * WSZ; proj.b[1] = bk; proj.y[1] = pk;
    proj.x[2] = cv; proj.w[2] = cw + 2 * WSZ; proj.b[2] = bv; proj.y[2] = pv;
    gemm_tf32_kernel<<<dim3(DOUT / 128, (BB * TQ) / 128, 3), 256,
                       GEMM_SMEM_BYTES>>>(proj, BB * TQ, DOUT, DIN);

    attn_tf32_kernel<<<dim3(TQ / 128, NH, BB), 128, ATTN_BYTES>>>(pq, pk, pv, px);

    GemmBatch oproj;
    oproj.x[0] = px; oproj.w[0] = cw + 3 * WSZ; oproj.b[0] = bo; oproj.y[0] = out;
    oproj.x[1] = px; oproj.w[1] = cw + 3 * WSZ; oproj.b[1] = bo; oproj.y[1] = out;
    oproj.x[2] = px; oproj.w[2] = cw + 3 * WSZ; oproj.b[2] = bo; oproj.y[2] = out;
    gemm_tf32_kernel<<<dim3(DOUT / 128, (BB * TQ) / 128, 1), 256,
                       GEMM_SMEM_BYTES>>>(oproj, BB * TQ, DOUT, DOUT);
}

// round 13
// speedup vs baseline: 1.2230x; 1.2230x over previous
#include <cuda_runtime.h>
#include <cstddef>
#include <cstdint>

#define BB 2
#define TQ 2048
#define TK 2048
#define DIN 1024
#define DOUT 1024
#define NH 16
#define HD 64

// Scratch (no cudaMalloc allowed).
__device__ float g_q[(size_t)BB * TQ * DOUT];   // projected Q (fp32)
__device__ float g_k[(size_t)BB * TK * DOUT];   // projected K (fp32)
__device__ float g_v[(size_t)BB * TK * DOUT];   // projected V (fp32)
__device__ float g_x[(size_t)BB * TQ * DOUT];   // attn out (tf32-valued)
__device__ float g_cq[(size_t)BB * TQ * DIN];   // tf32-converted inputs
__device__ float g_ck[(size_t)BB * TK * DIN];
__device__ float g_cv[(size_t)BB * TK * DIN];
__device__ float g_cw[(size_t)4 * DOUT * DIN];  // tf32-converted Wq,Wk,Wv,Wo

// ---------------------------------------------------------------------------
// helpers
// ---------------------------------------------------------------------------
__device__ __forceinline__ unsigned f2tf(float f) {
    unsigned r;
    asm("cvt.rna.tf32.f32 %0, %1;" : "=r"(r) : "f"(f));
    return r;
}

__device__ __forceinline__ float ex2(float x) {
    float r;
    asm("ex2.approx.f32 %0, %1;" : "=f"(r) : "f"(x));
    return r;
}

__device__ __forceinline__ void mma_tf32(float c[4],
                                         unsigned a0, unsigned a1, unsigned a2, unsigned a3,
                                         unsigned b0, unsigned b1) {
    asm volatile(
        "mma.sync.aligned.m16n8k8.row.col.f32.tf32.tf32.f32 "
        "{%0,%1,%2,%3}, {%4,%5,%6,%7}, {%8,%9}, {%0,%1,%2,%3};"
        : "+f"(c[0]), "+f"(c[1]), "+f"(c[2]), "+f"(c[3])
        : "r"(a0), "r"(a1), "r"(a2), "r"(a3), "r"(b0), "r"(b1));
}

// Streamed data: bypass L1 allocation (read-once from smem; keeps l1tex
// wavefront pressure down on the L1-bound kernels).
__device__ __forceinline__ void cp_async16(unsigned saddr, const void* g) {
    asm volatile("cp.async.cg.shared.global [%0], [%1], 16;" :: "r"(saddr), "l"(g));
}

__device__ __forceinline__ unsigned smem_u32(const void* p) {
    return (unsigned)__cvta_generic_to_shared(p);
}

__device__ __forceinline__ void ldsm_x4(unsigned& d0, unsigned& d1,
                                        unsigned& d2, unsigned& d3, unsigned addr) {
    asm volatile("ldmatrix.sync.aligned.m8n8.x4.shared.b16 {%0,%1,%2,%3}, [%4];"
                 : "=r"(d0), "=r"(d1), "=r"(d2), "=r"(d3) : "r"(addr));
}

// Pair-interleave one 8-wide k-group (attention K/Q path only).
__device__ __forceinline__ void sts_pair_group(unsigned* dst, float4 f0, float4 f1) {
    uint4 lo = {__float_as_uint(f0.x), __float_as_uint(f1.x),
                __float_as_uint(f0.y), __float_as_uint(f1.y)};
    uint4 hi = {__float_as_uint(f0.z), __float_as_uint(f1.z),
                __float_as_uint(f0.w), __float_as_uint(f1.w)};
    *(uint4*)dst = lo;
    *(uint4*)(dst + 4) = hi;
}
__device__ __forceinline__ void sts_pair_group_tf(unsigned* dst, float4 f0, float4 f1,
                                                  float sc) {
    uint4 lo = {f2tf(f0.x * sc), f2tf(f1.x * sc), f2tf(f0.y * sc), f2tf(f1.y * sc)};
    uint4 hi = {f2tf(f0.z * sc), f2tf(f1.z * sc), f2tf(f0.w * sc), f2tf(f1.w * sc)};
    *(uint4*)dst = lo;
    *(uint4*)(dst + 4) = hi;
}

// ---------------------------------------------------------------------------
// Elementwise tf32 pre-conversion (rna): ONE launch, 7 z-slices
// (3 activations + 4 weights), per-slice element counts.
// ---------------------------------------------------------------------------
struct CvtBatch {
    const float* src[7];
    float* dst[7];
    int n4[7];
};

__global__ __launch_bounds__(256) void cvt_tf32_kernel(CvtBatch p) {
    const float4* s = (const float4*)p.src[blockIdx.z];
    float4* d = (float4*)p.dst[blockIdx.z];
    const int n4 = p.n4[blockIdx.z];
    for (int i = blockIdx.x * 256 + threadIdx.x; i < n4; i += gridDim.x * 256) {
        float4 v = s[i];
        uint4 o = {f2tf(v.x), f2tf(v.y), f2tf(v.z), f2tf(v.w)};
        *(uint4*)(d + i) = o;
    }
}

// ---------------------------------------------------------------------------
// Batched GEMM + bias — R11 kernel (cp.async + LDSM, pre-converted operands).
// ---------------------------------------------------------------------------
#define GST 36
#define GEMM_BUF_WORDS (2 * 128 * GST)
#define GEMM_SMEM_BYTES (2 * GEMM_BUF_WORDS * 4)

struct GemmBatch {
    const float* x[3];
    const float* w[3];
    const float* b[3];
    float* y[3];
};

__global__ __launch_bounds__(256, 2) void gemm_tf32_kernel(
    GemmBatch p, int M, int N, int K) {
    extern __shared__ unsigned gsm[];
    const unsigned sb = smem_u32(gsm);

    const float* __restrict__ X = p.x[blockIdx.z];
    const float* __restrict__ W = p.w[blockIdx.z];
    const float* __restrict__ bias = p.b[blockIdx.z];
    float* __restrict__ Y = p.y[blockIdx.z];

    const int tid = threadIdx.x;
    const int lane = tid & 31;
    const int wid = tid >> 5;
    const int wm = wid >> 1;
    const int wn = wid & 1;
    const int g = lane >> 2;
    const int c = lane & 3;

    const int row0 = blockIdx.y * 128;
    const int col0 = blockIdx.x * 128;

    float acc[2][8][4];
#pragma unroll
    for (int mt = 0; mt < 2; mt++)
#pragma unroll
        for (int nt = 0; nt < 8; nt++)
#pragma unroll
            for (int j = 0; j < 4; j++) acc[mt][nt][j] = 0.0f;

    const int l7 = lane & 7;
    const int lb3 = (lane >> 3) & 1;
    const int lb4 = (lane >> 4) & 1;
    unsigned Aoff[2], Boff[4];
#pragma unroll
    for (int mt = 0; mt < 2; mt++) {
        int row = wm * 32 + mt * 16 + l7 + lb3 * 8;
        Aoff[mt] = (unsigned)((row * GST + lb4 * 4) * 4);
    }
#pragma unroll
    for (int pp = 0; pp < 4; pp++) {
        int row = wn * 64 + pp * 16 + l7 + lb4 * 8;
        Boff[pp] = (unsigned)((128 * GST + row * GST + lb3 * 4) * 4);
    }

    const int lrow = tid >> 3;
    const int lcol = (tid & 7) * 4;
    const int nslices = K >> 5;

    const float* xs = &X[(size_t)(row0 + lrow) * K + lcol];
    const float* ws = &W[(size_t)(col0 + lrow) * K + lcol];
    const unsigned aslot = (unsigned)((lrow * GST + lcol) * 4);
    const unsigned brow = (unsigned)(32 * GST * 4);
    const unsigned bofs = (unsigned)(128 * GST * 4);

#pragma unroll
    for (int i = 0; i < 4; i++) {
        cp_async16(sb + aslot + i * brow, xs + (size_t)i * 32 * K);
        cp_async16(sb + bofs + aslot + i * brow, ws + (size_t)i * 32 * K);
    }
    asm volatile("cp.async.commit_group;" ::: "memory");

    for (int t = 0; t < nslices; t++) {
        asm volatile("cp.async.wait_group 0;" ::: "memory");
        __syncthreads();

        if (t + 1 < nslices) {
            unsigned dst = sb + ((t + 1) & 1) * (unsigned)(GEMM_BUF_WORDS * 4);
            const float* xn = xs + (t + 1) * 32;
            const float* wn = ws + (t + 1) * 32;
#pragma unroll
            for (int i = 0; i < 4; i++) {
                cp_async16(dst + aslot + i * brow, xn + (size_t)i * 32 * K);
                cp_async16(dst + bofs + aslot + i * brow, wn + (size_t)i * 32 * K);
            }
            asm volatile("cp.async.commit_group;" ::: "memory");
        }

        const unsigned bufb = sb + (unsigned)((t & 1) * (GEMM_BUF_WORDS * 4));
#pragma unroll
        for (int ks = 0; ks < 4; ks++) {
            const unsigned kadd = (unsigned)(ks * 32);
            unsigned af0[4], af1[4], bf[8][2];
            ldsm_x4(af0[0], af0[1], af0[2], af0[3], bufb + Aoff[0] + kadd);
            ldsm_x4(af1[0], af1[1], af1[2], af1[3], bufb + Aoff[1] + kadd);
            ldsm_x4(bf[0][0], bf[0][1], bf[1][0], bf[1][1], bufb + Boff[0] + kadd);
            ldsm_x4(bf[2][0], bf[2][1], bf[3][0], bf[3][1], bufb + Boff[1] + kadd);
            ldsm_x4(bf[4][0], bf[4][1], bf[5][0], bf[5][1], bufb + Boff[2] + kadd);
            ldsm_x4(bf[6][0], bf[6][1], bf[7][0], bf[7][1], bufb + Boff[3] + kadd);
#pragma unroll
            for (int nt = 0; nt < 8; nt++) {
                mma_tf32(acc[0][nt], af0[0], af0[1], af0[2], af0[3], bf[nt][0], bf[nt][1]);
                mma_tf32(acc[1][nt], af1[0], af1[1], af1[2], af1[3], bf[nt][0], bf[nt][1]);
            }
        }
    }

#pragma unroll
    for (int mt = 0; mt < 2; mt++) {
        int r0 = row0 + wm * 32 + mt * 16 + g;
#pragma unroll
        for (int nt = 0; nt < 8; nt++) {
            int cc = col0 + wn * 64 + nt * 8 + c * 2;
            float b0 = bias[cc], b1 = bias[cc + 1];
            float2 lo = {acc[mt][nt][0] + b0, acc[mt][nt][1] + b1};
            float2 hi = {acc[mt][nt][2] + b0, acc[mt][nt][3] + b1};
            *(float2*)&Y[(size_t)r0 * N + cc] = lo;
            *(float2*)&Y[(size_t)(r0 + 8) * N + cc] = hi;
        }
    }
}

// ---------------------------------------------------------------------------
// Flash-attention — EXACT R11 kernel (312us measured, best passing config):
// 8 warps x 16q, fixed-max softmax, K reg-prefetch pair-interleaved,
// V cp.async permuted rows, s-registers as PV A-fragments, tf32 epilogue.
// ---------------------------------------------------------------------------
#define AST 72
#define SMQ 0
#define SMK (128 * AST)
#define SMV (128 * AST + 2 * 64 * AST)
#define ATTN_WORDS (128 * AST + 4 * 64 * AST)
#define ATTN_BYTES (ATTN_WORDS * 4)
#define NKT (TK / 64)

__global__ __launch_bounds__(256, 2) void attn_tf32_kernel(
    const float* __restrict__ gq, const float* __restrict__ gk,
    const float* __restrict__ gv, float* __restrict__ gx) {
    extern __shared__ unsigned sm[];
    unsigned* Qs = sm + SMQ;
    unsigned* Ksm = sm + SMK;
    unsigned* Vsm = sm + SMV;

    const int tid = threadIdx.x;
    const int lane = tid & 31;
    const int w = tid >> 5;
    const int g = lane >> 2;
    const int c = lane & 3;

    const int q0 = blockIdx.x * 128;
    const int h = blockIdx.y;
    const int b = blockIdx.z;

    const float SC = 0.125f * 1.44269504088896340736f;

    {
        const int qr = tid >> 1;
        const int qh = (tid & 1) * 32;
        const float* Qg = gq + ((size_t)b * TQ + q0 + qr) * DOUT + h * HD;
#pragma unroll
        for (int gi = 0; gi < 4; gi++) {
            int dc = qh + gi * 8;
            float4 f0 = *(const float4*)&Qg[dc];
            float4 f1 = *(const float4*)&Qg[dc + 4];
            sts_pair_group_tf(&Qs[qr * AST + dc], f0, f1, SC);
        }
    }

    const float* Kg = gk + (size_t)b * TK * DOUT + h * HD;
    const float* Vg = gv + (size_t)b * TK * DOUT + h * HD;

    const int key = tid >> 2;
    const int dcg = (tid & 3) * 16;
    const int srow = (key & 56) | (((key & 7) >> 1) + ((key & 1) << 2));

    float4 rk0, rk1, rk2, rk3;
    {
        const float* kp = &Kg[(size_t)key * DOUT + dcg];
        rk0 = *(const float4*)kp;
        rk1 = *(const float4*)(kp + 4);
        rk2 = *(const float4*)(kp + 8);
        rk3 = *(const float4*)(kp + 12);
        unsigned vdst = smem_u32(&Vsm[srow * AST + dcg]);
        const float* vp = &Vg[(size_t)key * DOUT + dcg];
#pragma unroll
        for (int j = 0; j < 4; j++) cp_async16(vdst + j * 16, vp + j * 4);
    }

    float o[8][4];
#pragma unroll
    for (int dt = 0; dt < 8; dt++)
#pragma unroll
        for (int j = 0; j < 4; j++) o[dt][j] = 0.0f;
    float lrow0 = 0.0f, lrow1 = 0.0f;

    for (int t = 0; t < NKT; t++) {
        const int cb = t & 1;
        unsigned* Kb = Ksm + cb * (64 * AST);
        unsigned* Vb = Vsm + cb * (64 * AST);

        sts_pair_group(&Kb[key * AST + dcg], rk0, rk1);
        sts_pair_group(&Kb[key * AST + dcg + 8], rk2, rk3);
        asm volatile("cp.async.wait_all;\n" ::: "memory");
        __syncthreads();

        if (t + 1 < NKT) {
            const float* kp = &Kg[(size_t)(t * 64 + 64 + key) * DOUT + dcg];
            rk0 = *(const float4*)kp;
            rk1 = *(const float4*)(kp + 4);
            rk2 = *(const float4*)(kp + 8);
            rk3 = *(const float4*)(kp + 12);
            unsigned* Vn = Vsm + (1 - cb) * (64 * AST);
            unsigned vdst = smem_u32(&Vn[srow * AST + dcg]);
            const float* vp = &Vg[(size_t)(t * 64 + 64 + key) * DOUT + dcg];
#pragma unroll
            for (int j = 0; j < 4; j++) cp_async16(vdst + j * 16, vp + j * 4);
        }

        float s[8][4];
#pragma unroll
        for (int nt = 0; nt < 8; nt++)
#pragma unroll
            for (int j = 0; j < 4; j++) s[nt][j] = 0.0f;
#pragma unroll
        for (int ks = 0; ks < 8; ks++) {
            const int kk = ks * 8;
            uint2 aA = *(const uint2*)&Qs[(w * 16 + g) * AST + kk + 2 * c];
            uint2 aB = *(const uint2*)&Qs[(w * 16 + g + 8) * AST + kk + 2 * c];
#pragma unroll
            for (int nt = 0; nt < 8; nt++) {
                uint2 bb = *(const uint2*)&Kb[(nt * 8 + g) * AST + kk + 2 * c];
                mma_tf32(s[nt], aA.x, aB.x, aA.y, aB.y, bb.x, bb.y);
            }
        }

#pragma unroll
        for (int nt = 0; nt < 8; nt++) {
            s[nt][0] = ex2(s[nt][0]);
            s[nt][1] = ex2(s[nt][1]);
            s[nt][2] = ex2(s[nt][2]);
            s[nt][3] = ex2(s[nt][3]);
            lrow0 += s[nt][0] + s[nt][1];
            lrow1 += s[nt][2] + s[nt][3];
        }

#pragma unroll
        for (int ks = 0; ks < 8; ks++) {
            unsigned a0 = __float_as_uint(s[ks][0]);
            unsigned a1 = __float_as_uint(s[ks][2]);
            unsigned a2 = __float_as_uint(s[ks][1]);
            unsigned a3 = __float_as_uint(s[ks][3]);
#pragma unroll
            for (int dt = 0; dt < 8; dt++) {
                unsigned b0 = Vb[(ks * 8 + c) * AST + dt * 8 + g];
                unsigned b1 = Vb[(ks * 8 + c + 4) * AST + dt * 8 + g];
                mma_tf32(o[dt], a0, a1, a2, a3, b0, b1);
            }
        }
    }

    lrow0 += __shfl_xor_sync(0xffffffffu, lrow0, 1);
    lrow0 += __shfl_xor_sync(0xffffffffu, lrow0, 2);
    lrow1 += __shfl_xor_sync(0xffffffffu, lrow1, 1);
    lrow1 += __shfl_xor_sync(0xffffffffu, lrow1, 2);

    float inv0 = 1.0f / lrow0, inv1 = 1.0f / lrow1;
    size_t r0 = (size_t)b * TQ + q0 + w * 16 + g;
#pragma unroll
    for (int dt = 0; dt < 8; dt++) {
        int cc = h * HD + dt * 8 + c * 2;
        uint2 lo = {f2tf(o[dt][0] * inv0), f2tf(o[dt][1] * inv0)};
        uint2 hi = {f2tf(o[dt][2] * inv1), f2tf(o[dt][3] * inv1)};
        *(uint2*)&gx[r0 * DOUT + cc] = lo;
        *(uint2*)&gx[(r0 + 8) * DOUT + cc] = hi;
    }
}

// ---------------------------------------------------------------------------
// Launch
// ---------------------------------------------------------------------------
extern "C" void kernel_launch(void* const* d_in, const int* in_sizes, int n_in,
                              void* d_out, int out_size) {
    const float* q  = (const float*)d_in[0];
    const float* k  = (const float*)d_in[1];
    const float* v  = (const float*)d_in[2];
    const float* Wq = (const float*)d_in[3];
    const float* bq = (const float*)d_in[4];
    const float* Wk = (const float*)d_in[5];
    const float* bk = (const float*)d_in[6];
    const float* Wv = (const float*)d_in[7];
    const float* bv = (const float*)d_in[8];
    const float* Wo = (const float*)d_in[9];
    const float* bo = (const float*)d_in[10];
    float* out = (float*)d_out;

    float *pq, *pk, *pv, *px, *cq, *ck, *cv, *cw;
    cudaGetSymbolAddress((void**)&pq, g_q);
    cudaGetSymbolAddress((void**)&pk, g_k);
    cudaGetSymbolAddress((void**)&pv, g_v);
    cudaGetSymbolAddress((void**)&px, g_x);
    cudaGetSymbolAddress((void**)&cq, g_cq);
    cudaGetSymbolAddress((void**)&ck, g_ck);
    cudaGetSymbolAddress((void**)&cv, g_cv);
    cudaGetSymbolAddress((void**)&cw, g_cw);

    cudaFuncSetAttribute(gemm_tf32_kernel,
                         cudaFuncAttributeMaxDynamicSharedMemorySize,
                         GEMM_SMEM_BYTES);
    cudaFuncSetAttribute(attn_tf32_kernel,
                         cudaFuncAttributeMaxDynamicSharedMemorySize,
                         ATTN_BYTES);

    const size_t WSZ = (size_t)DOUT * DIN;
    const int ACT4 = (int)((size_t)BB * TQ * DIN / 4);
    const int W4 = (int)(WSZ / 4);

    // Single cvt launch: 3 activation slices + 4 weight slices.
    CvtBatch cb;
    cb.src[0] = q;  cb.dst[0] = cq;            cb.n4[0] = ACT4;
    cb.src[1] = k;  cb.dst[1] = ck;            cb.n4[1] = ACT4;
    cb.src[2] = v;  cb.dst[2] = cv;            cb.n4[2] = ACT4;
    cb.src[3] = Wq; cb.dst[3] = cw + 0 * WSZ;  cb.n4[3] = W4;
    cb.src[4] = Wk; cb.dst[4] = cw + 1 * WSZ;  cb.n4[4] = W4;
    cb.src[5] = Wv; cb.dst[5] = cw + 2 * WSZ;  cb.n4[5] = W4;
    cb.src[6] = Wo; cb.dst[6] = cw + 3 * WSZ;  cb.n4[6] = W4;
    cvt_tf32_kernel<<<dim3(256, 1, 7), 256>>>(cb);

    GemmBatch proj;
    proj.x[0] = cq; proj.w[0] = cw + 0 * WSZ; proj.b[0] = bq; proj.y[0] = pq;
    proj.x[1] = ck; proj.w[1] = cw + 1 * WSZ; proj.b[1] = bk; proj.y[1] = pk;
    proj.x[2] = cv; proj.w[2] = cw + 2 * WSZ; proj.b[2] = bv; proj.y[2] = pv;
    gemm_tf32_kernel<<<dim3(DOUT / 128, (BB * TQ) / 128, 3), 256,
                       GEMM_SMEM_BYTES>>>(proj, BB * TQ, DOUT, DIN);

    attn_tf32_kernel<<<dim3(TQ / 128, NH, BB), 256, ATTN_BYTES>>>(pq, pk, pv, px);

    GemmBatch oproj;
    oproj.x[0] = px; oproj.w[0] = cw + 3 * WSZ; oproj.b[0] = bo; oproj.y[0] = out;
    oproj.x[1] = px; oproj.w[1] = cw + 3 * WSZ; oproj.b[1] = bo; oproj.y[1] = out;
    oproj.x[2] = px; oproj.w[2] = cw + 3 * WSZ; oproj.b[2] = bo; oproj.y[2] = out;
    gemm_tf32_kernel<<<dim3(DOUT / 128, (BB * TQ) / 128, 1), 256,
                       GEMM_SMEM_BYTES>>>(oproj, BB * TQ, DOUT, DOUT);
}